// round 1
// baseline (speedup 1.0000x reference)
#include <cuda_runtime.h>
#include <cuda_bf16.h>
#include <cstdint>

// ---------------------------------------------------------------------------
// SelfAttention: N=4096, D_IN=D_OUT=1024
//   Q = x@Wq ; K = x@Wk ; V = x@Wv          [4096,1024]
//   S = K @ Q^T                              [4096,4096]
//   P = softmax(S / 32, axis=-1)  (exp stored unnormalized, 1/rowsum folded
//                                  into the final GEMM epilogue)
//   out = P @ V                              [4096,1024]
// ---------------------------------------------------------------------------

#define NTOK  4096
#define DIM   1024
#define SOFTMAX_SCALE 0.03125f   // 1/sqrt(1024)

// Scratch (device globals: allocation-free per harness rules)
__device__ float g_Q[NTOK * DIM];
__device__ float g_K[NTOK * DIM];
__device__ float g_V[NTOK * DIM];
__device__ float g_S[(size_t)NTOK * NTOK];
__device__ float g_Rinv[NTOK];

// ---------------------------------------------------------------------------
// Tiled SGEMM: C[M,N] = A[M,K] @ B   (B row-major [K,N] if !BT, else B[N,K]^T)
// Block tile 128x128, K-tile 16, 256 threads, 8x8 per-thread micro-tile.
// Optional per-row scale applied in the epilogue (for softmax normalization).
// Requires M%128==0, N%128==0, K%16==0 (holds for all our shapes).
// ---------------------------------------------------------------------------
template <bool BT>
__global__ __launch_bounds__(256, 2)
void sgemm128(const float* __restrict__ A, const float* __restrict__ B,
              float* __restrict__ C, int M, int N, int K,
              const float* __restrict__ rowScale)
{
    __shared__ float As[16][128];
    __shared__ float Bs[16][128];

    const int bm = blockIdx.y * 128;
    const int bn = blockIdx.x * 128;
    const int tid = threadIdx.x;
    const int tx = tid & 15;        // 0..15  (col group)
    const int ty = tid >> 4;        // 0..15  (row group)

    // A-load mapping: 128 rows x 16 cols, float4 per thread, 2 passes
    const int arow = tid >> 2;            // 0..63
    const int acol = (tid & 3) * 4;       // 0,4,8,12
    // B-load mapping (NN): 16 rows x 128 cols
    const int brow = tid >> 5;            // 0..7
    const int bcol = (tid & 31) * 4;      // 0..124

    float acc[8][8];
#pragma unroll
    for (int i = 0; i < 8; i++)
#pragma unroll
        for (int j = 0; j < 8; j++) acc[i][j] = 0.f;

    for (int k0 = 0; k0 < K; k0 += 16) {
        // ---- load A tile (transpose into As[k][m]) ----
#pragma unroll
        for (int p = 0; p < 2; p++) {
            int r = arow + p * 64;
            float4 v = *(const float4*)&A[(size_t)(bm + r) * K + k0 + acol];
            As[acol + 0][r] = v.x;
            As[acol + 1][r] = v.y;
            As[acol + 2][r] = v.z;
            As[acol + 3][r] = v.w;
        }
        // ---- load B tile into Bs[k][n] ----
        if (BT) {
            // B is [N,K] row-major; Bs[k][n] = B[bn+n][k0+k]  (transpose store)
#pragma unroll
            for (int p = 0; p < 2; p++) {
                int r = arow + p * 64;
                float4 v = *(const float4*)&B[(size_t)(bn + r) * K + k0 + acol];
                Bs[acol + 0][r] = v.x;
                Bs[acol + 1][r] = v.y;
                Bs[acol + 2][r] = v.z;
                Bs[acol + 3][r] = v.w;
            }
        } else {
            // B is [K,N] row-major; direct float4 store
#pragma unroll
            for (int p = 0; p < 2; p++) {
                int r = brow + p * 8;
                float4 v = *(const float4*)&B[(size_t)(k0 + r) * N + bn + bcol];
                *(float4*)&Bs[r][bcol] = v;
            }
        }
        __syncthreads();

        // ---- compute ----
#pragma unroll
        for (int kk = 0; kk < 16; kk++) {
            float a[8], b[8];
            *(float4*)&a[0] = *(float4*)&As[kk][ty * 8];
            *(float4*)&a[4] = *(float4*)&As[kk][ty * 8 + 4];
            *(float4*)&b[0] = *(float4*)&Bs[kk][tx * 8];
            *(float4*)&b[4] = *(float4*)&Bs[kk][tx * 8 + 4];
#pragma unroll
            for (int i = 0; i < 8; i++)
#pragma unroll
                for (int j = 0; j < 8; j++)
                    acc[i][j] = fmaf(a[i], b[j], acc[i][j]);
        }
        __syncthreads();
    }

    // ---- epilogue (optional per-row scale) ----
#pragma unroll
    for (int i = 0; i < 8; i++) {
        int row = bm + ty * 8 + i;
        float rs = rowScale ? rowScale[row] : 1.0f;
#pragma unroll
        for (int j = 0; j < 8; j += 4) {
            float4 v;
            v.x = acc[i][j + 0] * rs;
            v.y = acc[i][j + 1] * rs;
            v.z = acc[i][j + 2] * rs;
            v.w = acc[i][j + 3] * rs;
            *(float4*)&C[(size_t)row * N + bn + tx * 8 + j] = v;
        }
    }
}

// ---------------------------------------------------------------------------
// Row softmax (unnormalized): S[row,:] <- exp((S - rowmax) * scale),
// Rinv[row] <- 1 / rowsum.  One block per row, 256 threads, row length 4096.
// ---------------------------------------------------------------------------
__global__ __launch_bounds__(256)
void softmax_rows(float* __restrict__ S, float* __restrict__ Rinv, int N)
{
    __shared__ float red[256];
    const int row = blockIdx.x;
    const int tid = threadIdx.x;
    float* r = S + (size_t)row * N;

    // pass 1: row max
    float mx = -3.402823466e38f;
    for (int j = tid; j < N; j += 256) mx = fmaxf(mx, r[j]);
    red[tid] = mx;
    __syncthreads();
#pragma unroll
    for (int s = 128; s > 0; s >>= 1) {
        if (tid < s) red[tid] = fmaxf(red[tid], red[tid + s]);
        __syncthreads();
    }
    mx = red[0];
    __syncthreads();

    // pass 2: exp + sum (store unnormalized exp back)
    float sum = 0.f;
    for (int j = tid; j < N; j += 256) {
        float e = __expf((r[j] - mx) * SOFTMAX_SCALE);
        r[j] = e;
        sum += e;
    }
    red[tid] = sum;
    __syncthreads();
#pragma unroll
    for (int s = 128; s > 0; s >>= 1) {
        if (tid < s) red[tid] += red[tid + s];
        __syncthreads();
    }
    if (tid == 0) Rinv[row] = 1.0f / red[0];
}

// ---------------------------------------------------------------------------
extern "C" void kernel_launch(void* const* d_in, const int* in_sizes, int n_in,
                              void* d_out, int out_size)
{
    const float* x  = (const float*)d_in[0];
    const float* Wq = (const float*)d_in[1];
    const float* Wk = (const float*)d_in[2];
    const float* Wv = (const float*)d_in[3];
    float* out = (float*)d_out;

    float *Q, *K, *V, *S, *Rinv;
    cudaGetSymbolAddress((void**)&Q,    g_Q);
    cudaGetSymbolAddress((void**)&K,    g_K);
    cudaGetSymbolAddress((void**)&V,    g_V);
    cudaGetSymbolAddress((void**)&S,    g_S);
    cudaGetSymbolAddress((void**)&Rinv, g_Rinv);

    dim3 blk(256);
    dim3 gridProj(DIM / 128, NTOK / 128);    // (8, 32)
    dim3 gridScore(NTOK / 128, NTOK / 128);  // (32, 32)

    // QKV projections
    sgemm128<false><<<gridProj, blk>>>(x, Wq, Q, NTOK, DIM, DIM, nullptr);
    sgemm128<false><<<gridProj, blk>>>(x, Wk, K, NTOK, DIM, DIM, nullptr);
    sgemm128<false><<<gridProj, blk>>>(x, Wv, V, NTOK, DIM, DIM, nullptr);

    // S = K @ Q^T
    sgemm128<true><<<gridScore, blk>>>(K, Q, S, NTOK, NTOK, DIM, nullptr);

    // exp + rowsum (normalization deferred to final GEMM epilogue)
    softmax_rows<<<NTOK, blk>>>(S, Rinv, NTOK);

    // out = P @ V with per-row 1/sum scaling
    sgemm128<false><<<gridProj, blk>>>(S, V, out, NTOK, DIM, NTOK, Rinv);
}

// round 3
// speedup vs baseline: 2.6367x; 2.6367x over previous
#include <cuda_runtime.h>
#include <cuda_bf16.h>
#include <cstdint>

// ---------------------------------------------------------------------------
// SelfAttention N=4096, D=1024 via mma.sync bf16 (hi/lo 3-pass fp32 emulation)
// (tcgen05 is unavailable: harness emits compute_100 PTX, no 'a' features)
//   split x, W^T -> bf16 hi/lo
//   Q,K,V = x@W      (mma.sync; epilogue splits Q,K to hi/lo; V stays fp32)
//   S = K@Q^T        (fp32 out)
//   P = exp(S/32 - max) -> hi/lo, Rinv = 1/rowsum
//   out = (P@V) * Rinv[row]   (V pre-transposed hi/lo)
// All GEMMs are NT: A[M,K] K-major, B[N,K] K-major.
// ---------------------------------------------------------------------------

#define NTOK 4096
#define DIM  1024
#define SOFTMAX_SCALE 0.03125f

#define BM 128
#define BN 128
#define BK 64
#define TILE_BYTES (BM * 128)                 // 128 rows x 128B = 16KB
#define OFF_AH 0
#define OFF_AL (1 * TILE_BYTES)
#define OFF_BH (2 * TILE_BYTES)
#define OFF_BL (3 * TILE_BYTES)
#define STAGE_BYTES (4 * TILE_BYTES)          // 64KB
#define SMEM_TOTAL (2 * STAGE_BYTES)          // 128KB

// ------------------------------- scratch -----------------------------------
__device__ __align__(256) __nv_bfloat16 g_xh[NTOK*DIM], g_xl[NTOK*DIM];
__device__ __align__(256) __nv_bfloat16 g_Wth[3][DIM*DIM], g_Wtl[3][DIM*DIM];
__device__ __align__(256) __nv_bfloat16 g_Qh[NTOK*DIM], g_Ql[NTOK*DIM];
__device__ __align__(256) __nv_bfloat16 g_Kh[NTOK*DIM], g_Kl[NTOK*DIM];
__device__ __align__(256) float         g_Vf[NTOK*DIM];
__device__ __align__(256) __nv_bfloat16 g_Vth[DIM*NTOK], g_Vtl[DIM*NTOK];
__device__ __align__(256) float         g_S[(size_t)NTOK*NTOK];
__device__ __align__(256) __nv_bfloat16 g_Ph[(size_t)NTOK*NTOK], g_Pl[(size_t)NTOK*NTOK];
__device__ __align__(256) float         g_Rinv[NTOK];

// ------------------------------- PTX helpers -------------------------------
__device__ __forceinline__ uint32_t smem_u32(const void* p) {
    uint32_t a;
    asm("{ .reg .u64 t; cvta.to.shared.u64 t, %1; cvt.u32.u64 %0, t; }" : "=r"(a) : "l"(p));
    return a;
}
#define CP_ASYNC16(dst, src) \
    asm volatile("cp.async.cg.shared.global [%0], [%1], 16;\n" :: "r"(dst), "l"(src))
#define CP_COMMIT()  asm volatile("cp.async.commit_group;\n" ::: "memory")
#define CP_WAIT(n)   asm volatile("cp.async.wait_group %0;\n" :: "n"(n) : "memory")

__device__ __forceinline__ void ldmatrix_x4(uint32_t* r, uint32_t addr) {
    asm volatile("ldmatrix.sync.aligned.m8n8.x4.shared.b16 {%0,%1,%2,%3}, [%4];"
                 : "=r"(r[0]), "=r"(r[1]), "=r"(r[2]), "=r"(r[3]) : "r"(addr));
}
__device__ __forceinline__ void mma16816(float* c, const uint32_t* a, const uint32_t* b) {
    asm volatile(
        "mma.sync.aligned.m16n8k16.row.col.f32.bf16.bf16.f32 "
        "{%0,%1,%2,%3}, {%4,%5,%6,%7}, {%8,%9}, {%0,%1,%2,%3};"
        : "+f"(c[0]), "+f"(c[1]), "+f"(c[2]), "+f"(c[3])
        : "r"(a[0]), "r"(a[1]), "r"(a[2]), "r"(a[3]), "r"(b[0]), "r"(b[1]));
}

// ------------------------- tile loader (cp.async) --------------------------
// Load nrows x 64 bf16 (128B/row) with SW128-style XOR swizzle.
__device__ __forceinline__ void load_tile(uint32_t dst, const __nv_bfloat16* src,
                                          int ld, int tid) {
    const int n16 = BM * 8;  // 16B chunks
    for (int i = tid; i < n16; i += 256) {
        int r = i >> 3, c = i & 7;
        uint32_t off = (uint32_t)(r * 128) + (uint32_t)((c * 16) ^ ((r & 7) * 16));
        CP_ASYNC16(dst + off, src + (size_t)r * ld + c * 8);
    }
}

// --------------------------- GEMM (hi/lo x 3) -------------------------------
// C[M,N] = (Ah+Al)[M,K] @ (Bh+Bl)[N,K]^T   (both K-major bf16)
// EPI=0: fp32 out (optional per-row scale); EPI=1: split to bf16 hi/lo out
template <int EPI>
__global__ __launch_bounds__(256, 1)
void gemm_hl(const __nv_bfloat16* __restrict__ Ah, const __nv_bfloat16* __restrict__ Al,
             const __nv_bfloat16* __restrict__ Bh, const __nv_bfloat16* __restrict__ Bl,
             int Kdim, int ldC,
             float* __restrict__ Cf,
             __nv_bfloat16* __restrict__ Ch, __nv_bfloat16* __restrict__ Cl,
             const float* __restrict__ rowScale)
{
    extern __shared__ char smem[];
    const uint32_t sbase = smem_u32(smem);
    const int tid = threadIdx.x;
    const int wid = tid >> 5;
    const int lane = tid & 31;
    const int wm = wid >> 2;       // 0..1  (64-row slab)
    const int wn = wid & 3;        // 0..3  (32-col slab)
    const int bm = blockIdx.y * BM;
    const int bn = blockIdx.x * BN;
    const int NC = Kdim / BK;

    // per-lane ldmatrix addressing (rows fixed per fragment tile)
    const int aRow  = wm * 64 + (lane & 15);               // + mi*16
    const int aColb = ((lane >> 4) & 1) * 16;              // + ks*32
    const int bRow  = wn * 32 + (lane & 7) + ((lane >> 4) & 1) * 8;  // + p*16
    const int bColb = ((lane >> 3) & 1) * 16;              // + ks*32

    const __nv_bfloat16* a_h = Ah + (size_t)bm * Kdim;
    const __nv_bfloat16* a_l = Al + (size_t)bm * Kdim;
    const __nv_bfloat16* b_h = Bh + (size_t)bn * Kdim;
    const __nv_bfloat16* b_l = Bl + (size_t)bn * Kdim;

    float acc[4][4][4];
#pragma unroll
    for (int i = 0; i < 4; i++)
#pragma unroll
        for (int j = 0; j < 4; j++)
#pragma unroll
            for (int r = 0; r < 4; r++) acc[i][j][r] = 0.f;

    // prologue: stage 0 <- chunk 0, stage 1 <- chunk 1
#pragma unroll
    for (int s = 0; s < 2; s++) {
        uint32_t sb = sbase + s * STAGE_BYTES;
        load_tile(sb + OFF_AH, a_h + s * BK, Kdim, tid);
        load_tile(sb + OFF_AL, a_l + s * BK, Kdim, tid);
        load_tile(sb + OFF_BH, b_h + s * BK, Kdim, tid);
        load_tile(sb + OFF_BL, b_l + s * BK, Kdim, tid);
        CP_COMMIT();
    }

    for (int kc = 0; kc < NC; kc++) {
        const int s = kc & 1;
        if (kc == NC - 1) { CP_WAIT(0); } else { CP_WAIT(1); }
        __syncthreads();

        const uint32_t sb = sbase + s * STAGE_BYTES;
#pragma unroll
        for (int ks = 0; ks < 4; ks++) {
            // B fragments: 2x ldmatrix.x4 per hi/lo covering 4 n8-tiles
            uint32_t bh[4][2], bl[4][2];
#pragma unroll
            for (int p = 0; p < 2; p++) {
                int r = bRow + p * 16;
                uint32_t off = (uint32_t)(r * 128) +
                               (uint32_t)(((ks * 32) + bColb) ^ ((r & 7) * 16));
                uint32_t t[4];
                ldmatrix_x4(t, sb + OFF_BH + off);
                bh[2 * p][0] = t[0]; bh[2 * p][1] = t[1];
                bh[2 * p + 1][0] = t[2]; bh[2 * p + 1][1] = t[3];
                ldmatrix_x4(t, sb + OFF_BL + off);
                bl[2 * p][0] = t[0]; bl[2 * p][1] = t[1];
                bl[2 * p + 1][0] = t[2]; bl[2 * p + 1][1] = t[3];
            }
#pragma unroll
            for (int mi = 0; mi < 4; mi++) {
                int r = aRow + mi * 16;
                uint32_t off = (uint32_t)(r * 128) +
                               (uint32_t)(((ks * 32) + aColb) ^ ((r & 7) * 16));
                uint32_t ah[4], al[4];
                ldmatrix_x4(ah, sb + OFF_AH + off);
                ldmatrix_x4(al, sb + OFF_AL + off);
#pragma unroll
                for (int ni = 0; ni < 4; ni++) {
                    mma16816(acc[mi][ni], ah, bh[ni]);
                    mma16816(acc[mi][ni], ah, bl[ni]);
                    mma16816(acc[mi][ni], al, bh[ni]);
                }
            }
        }
        __syncthreads();

        if (kc + 2 < NC) {
            uint32_t sb2 = sbase + s * STAGE_BYTES;
            int kk = (kc + 2) * BK;
            load_tile(sb2 + OFF_AH, a_h + kk, Kdim, tid);
            load_tile(sb2 + OFF_AL, a_l + kk, Kdim, tid);
            load_tile(sb2 + OFF_BH, b_h + kk, Kdim, tid);
            load_tile(sb2 + OFF_BL, b_l + kk, Kdim, tid);
            CP_COMMIT();
        }
    }

    // ---- epilogue ----
    const int cRowBase = bm + wm * 64 + (lane >> 2);
    const int cColBase = bn + wn * 32 + (lane & 3) * 2;
#pragma unroll
    for (int mi = 0; mi < 4; mi++) {
        const int r0 = cRowBase + mi * 16;
        const int r1 = r0 + 8;
        float rs0 = 1.f, rs1 = 1.f;
        if (EPI == 0 && rowScale) { rs0 = rowScale[r0]; rs1 = rowScale[r1]; }
#pragma unroll
        for (int ni = 0; ni < 4; ni++) {
            const int col = cColBase + ni * 8;
            const float* d = acc[mi][ni];
            if (EPI == 0) {
                float2 v0 = make_float2(d[0] * rs0, d[1] * rs0);
                float2 v1 = make_float2(d[2] * rs1, d[3] * rs1);
                *(float2*)&Cf[(size_t)r0 * ldC + col] = v0;
                *(float2*)&Cf[(size_t)r1 * ldC + col] = v1;
            } else {
                __nv_bfloat162 hv, lv;
                hv.x = __float2bfloat16_rn(d[0]);
                hv.y = __float2bfloat16_rn(d[1]);
                lv.x = __float2bfloat16_rn(d[0] - __bfloat162float(hv.x));
                lv.y = __float2bfloat16_rn(d[1] - __bfloat162float(hv.y));
                *(__nv_bfloat162*)&Ch[(size_t)r0 * ldC + col] = hv;
                *(__nv_bfloat162*)&Cl[(size_t)r0 * ldC + col] = lv;
                hv.x = __float2bfloat16_rn(d[2]);
                hv.y = __float2bfloat16_rn(d[3]);
                lv.x = __float2bfloat16_rn(d[2] - __bfloat162float(hv.x));
                lv.y = __float2bfloat16_rn(d[3] - __bfloat162float(hv.y));
                *(__nv_bfloat162*)&Ch[(size_t)r1 * ldC + col] = hv;
                *(__nv_bfloat162*)&Cl[(size_t)r1 * ldC + col] = lv;
            }
        }
    }
}

// ----------------------------- aux kernels ---------------------------------
__global__ __launch_bounds__(256)
void split_f32(const float* __restrict__ src, __nv_bfloat16* __restrict__ dh,
               __nv_bfloat16* __restrict__ dl, int n4)
{
    int i = blockIdx.x * blockDim.x + threadIdx.x;
    if (i >= n4) return;
    float4 v = ((const float4*)src)[i];
    __nv_bfloat162 h0, h1, l0, l1;
    h0.x = __float2bfloat16_rn(v.x); h0.y = __float2bfloat16_rn(v.y);
    h1.x = __float2bfloat16_rn(v.z); h1.y = __float2bfloat16_rn(v.w);
    l0.x = __float2bfloat16_rn(v.x - __bfloat162float(h0.x));
    l0.y = __float2bfloat16_rn(v.y - __bfloat162float(h0.y));
    l1.x = __float2bfloat16_rn(v.z - __bfloat162float(h1.x));
    l1.y = __float2bfloat16_rn(v.w - __bfloat162float(h1.y));
    ((__nv_bfloat162*)dh)[i * 2 + 0] = h0;
    ((__nv_bfloat162*)dh)[i * 2 + 1] = h1;
    ((__nv_bfloat162*)dl)[i * 2 + 0] = l0;
    ((__nv_bfloat162*)dl)[i * 2 + 1] = l1;
}

// dst[C,R] (bf16 hi/lo) = transpose(src[R,C] fp32)
__global__ __launch_bounds__(256)
void transpose_split(const float* __restrict__ src, __nv_bfloat16* __restrict__ dh,
                     __nv_bfloat16* __restrict__ dl, int R, int C)
{
    __shared__ float t[32][33];
    const int bx = blockIdx.x * 32;
    const int by = blockIdx.y * 32;
    const int x = threadIdx.x, y = threadIdx.y;  // (32, 8)
#pragma unroll
    for (int i = 0; i < 32; i += 8)
        t[y + i][x] = src[(size_t)(by + y + i) * C + bx + x];
    __syncthreads();
#pragma unroll
    for (int i = 0; i < 32; i += 8) {
        float v = t[x][y + i];
        __nv_bfloat16 h = __float2bfloat16_rn(v);
        __nv_bfloat16 l = __float2bfloat16_rn(v - __bfloat162float(h));
        size_t o = (size_t)(bx + y + i) * R + by + x;
        dh[o] = h;
        dl[o] = l;
    }
}

__global__ __launch_bounds__(256)
void softmax_split(const float* __restrict__ S, __nv_bfloat16* __restrict__ Ph,
                   __nv_bfloat16* __restrict__ Pl, float* __restrict__ Rinv, int N)
{
    __shared__ float red[256];
    const int row = blockIdx.x;
    const int tid = threadIdx.x;
    const float* r = S + (size_t)row * N;

    float mx = -3.402823466e38f;
    for (int j = tid; j < N; j += 256) mx = fmaxf(mx, r[j]);
    red[tid] = mx;
    __syncthreads();
#pragma unroll
    for (int s = 128; s > 0; s >>= 1) {
        if (tid < s) red[tid] = fmaxf(red[tid], red[tid + s]);
        __syncthreads();
    }
    mx = red[0];
    __syncthreads();

    float sum = 0.f;
    for (int j = tid; j < N; j += 256) {
        float e = __expf((r[j] - mx) * SOFTMAX_SCALE);
        sum += e;
        __nv_bfloat16 h = __float2bfloat16_rn(e);
        __nv_bfloat16 l = __float2bfloat16_rn(e - __bfloat162float(h));
        Ph[(size_t)row * N + j] = h;
        Pl[(size_t)row * N + j] = l;
    }
    red[tid] = sum;
    __syncthreads();
#pragma unroll
    for (int s = 128; s > 0; s >>= 1) {
        if (tid < s) red[tid] += red[tid + s];
        __syncthreads();
    }
    if (tid == 0) Rinv[row] = 1.0f / red[0];
}

// ------------------------------- driver ------------------------------------
extern "C" void kernel_launch(void* const* d_in, const int* in_sizes, int n_in,
                              void* d_out, int out_size)
{
    const float* x  = (const float*)d_in[0];
    const float* Wq = (const float*)d_in[1];
    const float* Wk = (const float*)d_in[2];
    const float* Wv = (const float*)d_in[3];
    float* out = (float*)d_out;

    __nv_bfloat16 *xh, *xl, *Wth, *Wtl, *Qh, *Ql, *Kh, *Kl, *Vth, *Vtl, *Ph, *Pl;
    float *Vf, *S, *Rinv;
    cudaGetSymbolAddress((void**)&xh, g_xh);   cudaGetSymbolAddress((void**)&xl, g_xl);
    cudaGetSymbolAddress((void**)&Wth, g_Wth); cudaGetSymbolAddress((void**)&Wtl, g_Wtl);
    cudaGetSymbolAddress((void**)&Qh, g_Qh);   cudaGetSymbolAddress((void**)&Ql, g_Ql);
    cudaGetSymbolAddress((void**)&Kh, g_Kh);   cudaGetSymbolAddress((void**)&Kl, g_Kl);
    cudaGetSymbolAddress((void**)&Vf, g_Vf);
    cudaGetSymbolAddress((void**)&Vth, g_Vth); cudaGetSymbolAddress((void**)&Vtl, g_Vtl);
    cudaGetSymbolAddress((void**)&S, g_S);
    cudaGetSymbolAddress((void**)&Ph, g_Ph);   cudaGetSymbolAddress((void**)&Pl, g_Pl);
    cudaGetSymbolAddress((void**)&Rinv, g_Rinv);

    cudaFuncSetAttribute(gemm_hl<0>, cudaFuncAttributeMaxDynamicSharedMemorySize, SMEM_TOTAL);
    cudaFuncSetAttribute(gemm_hl<1>, cudaFuncAttributeMaxDynamicSharedMemorySize, SMEM_TOTAL);

    // 1. split x ; transpose+split weights (W[K,N] -> W^T[N,K])
    split_f32<<<(NTOK * DIM / 4 + 255) / 256, 256>>>(x, xh, xl, NTOK * DIM / 4);
    dim3 tb(32, 8);
    transpose_split<<<dim3(DIM / 32, DIM / 32), tb>>>(Wq, Wth + 0 * DIM * DIM, Wtl + 0 * DIM * DIM, DIM, DIM);
    transpose_split<<<dim3(DIM / 32, DIM / 32), tb>>>(Wk, Wth + 1 * DIM * DIM, Wtl + 1 * DIM * DIM, DIM, DIM);
    transpose_split<<<dim3(DIM / 32, DIM / 32), tb>>>(Wv, Wth + 2 * DIM * DIM, Wtl + 2 * DIM * DIM, DIM, DIM);

    // 2. projections
    dim3 blk(256);
    dim3 gProj(DIM / BN, NTOK / BM);   // (8, 32)
    gemm_hl<1><<<gProj, blk, SMEM_TOTAL>>>(xh, xl, Wth + 0 * DIM * DIM, Wtl + 0 * DIM * DIM,
                                           DIM, DIM, nullptr, Qh, Ql, nullptr);
    gemm_hl<1><<<gProj, blk, SMEM_TOTAL>>>(xh, xl, Wth + 1 * DIM * DIM, Wtl + 1 * DIM * DIM,
                                           DIM, DIM, nullptr, Kh, Kl, nullptr);
    gemm_hl<0><<<gProj, blk, SMEM_TOTAL>>>(xh, xl, Wth + 2 * DIM * DIM, Wtl + 2 * DIM * DIM,
                                           DIM, DIM, Vf, nullptr, nullptr, nullptr);

    // 3. V^T hi/lo  [DIM, NTOK]
    transpose_split<<<dim3(DIM / 32, NTOK / 32), tb>>>(Vf, Vth, Vtl, NTOK, DIM);

    // 4. S = K @ Q^T   [NTOK, NTOK]
    dim3 gS(NTOK / BN, NTOK / BM);     // (32, 32)
    gemm_hl<0><<<gS, blk, SMEM_TOTAL>>>(Kh, Kl, Qh, Ql, DIM, NTOK, S, nullptr, nullptr, nullptr);

    // 5. softmax -> P hi/lo + Rinv
    softmax_split<<<NTOK, 256>>>(S, Ph, Pl, Rinv, NTOK);

    // 6. out = (P @ V) * Rinv
    gemm_hl<0><<<gProj, blk, SMEM_TOTAL>>>(Ph, Pl, Vth, Vtl, NTOK, DIM, out,
                                           nullptr, nullptr, Rinv);
}

// round 5
// speedup vs baseline: 2.9962x; 1.1364x over previous
#include <cuda_runtime.h>
#include <cuda_bf16.h>
#include <cstdint>

// ---------------------------------------------------------------------------
// SelfAttention N=4096, D=1024 via mma.sync bf16 (hi/lo 3-pass fp32 emulation)
//   split x, W^T -> bf16 hi/lo
//   Q,K,V = x@W      (epilogue splits Q,K to hi/lo; V stays fp32)
//   S = K@Q^T        (fp32 out)
//   P = exp(S/32 - max) -> hi/lo, Rinv = 1/rowsum
//   out = (P@V) * Rinv[row]   (V pre-transposed hi/lo)
// All GEMMs NT: A[M,K] K-major, B[N,K] K-major.
// R4 (resubmit after infra failure): BN=256, 64x64 warp tiles (8 warps),
// 2-stage 192KB smem.
// ---------------------------------------------------------------------------

#define NTOK 4096
#define DIM  1024
#define SOFTMAX_SCALE 0.03125f

#define BM 128
#define BN 256
#define BK 64
#define A_TILE (BM * 128)                     // 16KB
#define B_TILE (BN * 128)                     // 32KB
#define OFF_AH 0
#define OFF_AL (A_TILE)
#define OFF_BH (2 * A_TILE)
#define OFF_BL (2 * A_TILE + B_TILE)
#define STAGE_BYTES (2 * A_TILE + 2 * B_TILE) // 96KB
#define SMEM_TOTAL (2 * STAGE_BYTES)          // 192KB

// ------------------------------- scratch -----------------------------------
__device__ __align__(256) __nv_bfloat16 g_xh[NTOK*DIM], g_xl[NTOK*DIM];
__device__ __align__(256) __nv_bfloat16 g_Wth[3][DIM*DIM], g_Wtl[3][DIM*DIM];
__device__ __align__(256) __nv_bfloat16 g_Qh[NTOK*DIM], g_Ql[NTOK*DIM];
__device__ __align__(256) __nv_bfloat16 g_Kh[NTOK*DIM], g_Kl[NTOK*DIM];
__device__ __align__(256) float         g_Vf[NTOK*DIM];
__device__ __align__(256) __nv_bfloat16 g_Vth[DIM*NTOK], g_Vtl[DIM*NTOK];
__device__ __align__(256) float         g_S[(size_t)NTOK*NTOK];
__device__ __align__(256) __nv_bfloat16 g_Ph[(size_t)NTOK*NTOK], g_Pl[(size_t)NTOK*NTOK];
__device__ __align__(256) float         g_Rinv[NTOK];

// ------------------------------- PTX helpers -------------------------------
__device__ __forceinline__ uint32_t smem_u32(const void* p) {
    uint32_t a;
    asm("{ .reg .u64 t; cvta.to.shared.u64 t, %1; cvt.u32.u64 %0, t; }" : "=r"(a) : "l"(p));
    return a;
}
#define CP_ASYNC16(dst, src) \
    asm volatile("cp.async.cg.shared.global [%0], [%1], 16;\n" :: "r"(dst), "l"(src))
#define CP_COMMIT()  asm volatile("cp.async.commit_group;\n" ::: "memory")
#define CP_WAIT(n)   asm volatile("cp.async.wait_group %0;\n" :: "n"(n) : "memory")

__device__ __forceinline__ void ldmatrix_x4(uint32_t* r, uint32_t addr) {
    asm volatile("ldmatrix.sync.aligned.m8n8.x4.shared.b16 {%0,%1,%2,%3}, [%4];"
                 : "=r"(r[0]), "=r"(r[1]), "=r"(r[2]), "=r"(r[3]) : "r"(addr));
}
__device__ __forceinline__ void mma16816(float* c, const uint32_t* a, const uint32_t* b) {
    asm volatile(
        "mma.sync.aligned.m16n8k16.row.col.f32.bf16.bf16.f32 "
        "{%0,%1,%2,%3}, {%4,%5,%6,%7}, {%8,%9}, {%0,%1,%2,%3};"
        : "+f"(c[0]), "+f"(c[1]), "+f"(c[2]), "+f"(c[3])
        : "r"(a[0]), "r"(a[1]), "r"(a[2]), "r"(a[3]), "r"(b[0]), "r"(b[1]));
}

// ------------------------- tile loaders (cp.async) -------------------------
// Load nrows x 64 bf16 (128B/row) with SW128-style XOR swizzle; 256 threads.
template <int NROWS>
__device__ __forceinline__ void load_tile(uint32_t dst, const __nv_bfloat16* src,
                                          int ld, int tid) {
    const int n16 = NROWS * 8;
#pragma unroll
    for (int i = tid; i < n16; i += 256) {
        int r = i >> 3, c = i & 7;
        uint32_t off = (uint32_t)(r * 128) + (uint32_t)((c * 16) ^ ((r & 7) * 16));
        CP_ASYNC16(dst + off, src + (size_t)r * ld + c * 8);
    }
}

// --------------------------- GEMM (hi/lo x 3) -------------------------------
// C[M,N] = (Ah+Al)[M,K] @ (Bh+Bl)[N,K]^T
// EPI=0: fp32 out (optional per-row scale); EPI=1: split bf16 hi/lo out
template <int EPI>
__global__ __launch_bounds__(256, 1)
void gemm_hl(const __nv_bfloat16* __restrict__ Ah, const __nv_bfloat16* __restrict__ Al,
             const __nv_bfloat16* __restrict__ Bh, const __nv_bfloat16* __restrict__ Bl,
             int Kdim, int ldC,
             float* __restrict__ Cf,
             __nv_bfloat16* __restrict__ Ch, __nv_bfloat16* __restrict__ Cl,
             const float* __restrict__ rowScale)
{
    extern __shared__ char smem[];
    const uint32_t sbase = smem_u32(smem);
    const int tid = threadIdx.x;
    const int wid = tid >> 5;
    const int lane = tid & 31;
    const int wm = wid >> 2;       // 0..1  (64-row slab)
    const int wn = wid & 3;        // 0..3  (64-col slab)
    const int bm = blockIdx.y * BM;
    const int bn = blockIdx.x * BN;
    const int NC = Kdim / BK;

    // per-lane ldmatrix addressing
    const int aRow  = wm * 64 + (lane & 15);                          // + mi*16
    const int aColb = ((lane >> 4) & 1) * 16;                         // + ks*32
    const int bRow  = wn * 64 + (lane & 7) + ((lane >> 4) & 1) * 8;   // + p*16
    const int bColb = ((lane >> 3) & 1) * 16;                         // + ks*32

    const __nv_bfloat16* a_h = Ah + (size_t)bm * Kdim;
    const __nv_bfloat16* a_l = Al + (size_t)bm * Kdim;
    const __nv_bfloat16* b_h = Bh + (size_t)bn * Kdim;
    const __nv_bfloat16* b_l = Bl + (size_t)bn * Kdim;

    float acc[4][8][4];
#pragma unroll
    for (int i = 0; i < 4; i++)
#pragma unroll
        for (int j = 0; j < 8; j++)
#pragma unroll
            for (int r = 0; r < 4; r++) acc[i][j][r] = 0.f;

    // prologue: stage 0 <- chunk 0, stage 1 <- chunk 1
#pragma unroll
    for (int s = 0; s < 2; s++) {
        uint32_t sb = sbase + s * STAGE_BYTES;
        load_tile<BM>(sb + OFF_AH, a_h + s * BK, Kdim, tid);
        load_tile<BM>(sb + OFF_AL, a_l + s * BK, Kdim, tid);
        load_tile<BN>(sb + OFF_BH, b_h + s * BK, Kdim, tid);
        load_tile<BN>(sb + OFF_BL, b_l + s * BK, Kdim, tid);
        CP_COMMIT();
    }

    for (int kc = 0; kc < NC; kc++) {
        const int s = kc & 1;
        if (kc == NC - 1) { CP_WAIT(0); } else { CP_WAIT(1); }
        __syncthreads();

        const uint32_t sb = sbase + s * STAGE_BYTES;
#pragma unroll
        for (int ks = 0; ks < 4; ks++) {
            // B fragments: 8 n8-tiles, hi+lo (4 ldmatrix.x4 each)
            uint32_t bh[8][2], bl[8][2];
#pragma unroll
            for (int p = 0; p < 4; p++) {
                int r = bRow + p * 16;
                uint32_t off = (uint32_t)(r * 128) +
                               (uint32_t)(((ks * 32) + bColb) ^ ((r & 7) * 16));
                uint32_t t[4];
                ldmatrix_x4(t, sb + OFF_BH + off);
                bh[2 * p][0] = t[0]; bh[2 * p][1] = t[1];
                bh[2 * p + 1][0] = t[2]; bh[2 * p + 1][1] = t[3];
                ldmatrix_x4(t, sb + OFF_BL + off);
                bl[2 * p][0] = t[0]; bl[2 * p][1] = t[1];
                bl[2 * p + 1][0] = t[2]; bl[2 * p + 1][1] = t[3];
            }
#pragma unroll
            for (int mi = 0; mi < 4; mi++) {
                int r = aRow + mi * 16;
                uint32_t off = (uint32_t)(r * 128) +
                               (uint32_t)(((ks * 32) + aColb) ^ ((r & 7) * 16));
                uint32_t ah[4], al[4];
                ldmatrix_x4(ah, sb + OFF_AH + off);
                ldmatrix_x4(al, sb + OFF_AL + off);
#pragma unroll
                for (int ni = 0; ni < 8; ni++) {
                    mma16816(acc[mi][ni], ah, bh[ni]);
                    mma16816(acc[mi][ni], ah, bl[ni]);
                    mma16816(acc[mi][ni], al, bh[ni]);
                }
            }
        }
        __syncthreads();

        if (kc + 2 < NC) {
            uint32_t sb2 = sbase + s * STAGE_BYTES;
            int kk = (kc + 2) * BK;
            load_tile<BM>(sb2 + OFF_AH, a_h + kk, Kdim, tid);
            load_tile<BM>(sb2 + OFF_AL, a_l + kk, Kdim, tid);
            load_tile<BN>(sb2 + OFF_BH, b_h + kk, Kdim, tid);
            load_tile<BN>(sb2 + OFF_BL, b_l + kk, Kdim, tid);
            CP_COMMIT();
        }
    }

    // ---- epilogue ----
    const int cRowBase = bm + wm * 64 + (lane >> 2);
    const int cColBase = bn + wn * 64 + (lane & 3) * 2;
#pragma unroll
    for (int mi = 0; mi < 4; mi++) {
        const int r0 = cRowBase + mi * 16;
        const int r1 = r0 + 8;
        float rs0 = 1.f, rs1 = 1.f;
        if (EPI == 0 && rowScale) { rs0 = rowScale[r0]; rs1 = rowScale[r1]; }
#pragma unroll
        for (int ni = 0; ni < 8; ni++) {
            const int col = cColBase + ni * 8;
            const float* d = acc[mi][ni];
            if (EPI == 0) {
                float2 v0 = make_float2(d[0] * rs0, d[1] * rs0);
                float2 v1 = make_float2(d[2] * rs1, d[3] * rs1);
                *(float2*)&Cf[(size_t)r0 * ldC + col] = v0;
                *(float2*)&Cf[(size_t)r1 * ldC + col] = v1;
            } else {
                __nv_bfloat162 hv, lv;
                hv.x = __float2bfloat16_rn(d[0]);
                hv.y = __float2bfloat16_rn(d[1]);
                lv.x = __float2bfloat16_rn(d[0] - __bfloat162float(hv.x));
                lv.y = __float2bfloat16_rn(d[1] - __bfloat162float(hv.y));
                *(__nv_bfloat162*)&Ch[(size_t)r0 * ldC + col] = hv;
                *(__nv_bfloat162*)&Cl[(size_t)r0 * ldC + col] = lv;
                hv.x = __float2bfloat16_rn(d[2]);
                hv.y = __float2bfloat16_rn(d[3]);
                lv.x = __float2bfloat16_rn(d[2] - __bfloat162float(hv.x));
                lv.y = __float2bfloat16_rn(d[3] - __bfloat162float(hv.y));
                *(__nv_bfloat162*)&Ch[(size_t)r1 * ldC + col] = hv;
                *(__nv_bfloat162*)&Cl[(size_t)r1 * ldC + col] = lv;
            }
        }
    }
}

// ----------------------------- aux kernels ---------------------------------
__global__ __launch_bounds__(256)
void split_f32(const float* __restrict__ src, __nv_bfloat16* __restrict__ dh,
               __nv_bfloat16* __restrict__ dl, int n4)
{
    int i = blockIdx.x * blockDim.x + threadIdx.x;
    if (i >= n4) return;
    float4 v = ((const float4*)src)[i];
    __nv_bfloat162 h0, h1, l0, l1;
    h0.x = __float2bfloat16_rn(v.x); h0.y = __float2bfloat16_rn(v.y);
    h1.x = __float2bfloat16_rn(v.z); h1.y = __float2bfloat16_rn(v.w);
    l0.x = __float2bfloat16_rn(v.x - __bfloat162float(h0.x));
    l0.y = __float2bfloat16_rn(v.y - __bfloat162float(h0.y));
    l1.x = __float2bfloat16_rn(v.z - __bfloat162float(h1.x));
    l1.y = __float2bfloat16_rn(v.w - __bfloat162float(h1.y));
    ((__nv_bfloat162*)dh)[i * 2 + 0] = h0;
    ((__nv_bfloat162*)dh)[i * 2 + 1] = h1;
    ((__nv_bfloat162*)dl)[i * 2 + 0] = l0;
    ((__nv_bfloat162*)dl)[i * 2 + 1] = l1;
}

// dst[C,R] (bf16 hi/lo) = transpose(src[R,C] fp32)
__global__ __launch_bounds__(256)
void transpose_split(const float* __restrict__ src, __nv_bfloat16* __restrict__ dh,
                     __nv_bfloat16* __restrict__ dl, int R, int C)
{
    __shared__ float t[32][33];
    const int bx = blockIdx.x * 32;
    const int by = blockIdx.y * 32;
    const int x = threadIdx.x, y = threadIdx.y;  // (32, 8)
#pragma unroll
    for (int i = 0; i < 32; i += 8)
        t[y + i][x] = src[(size_t)(by + y + i) * C + bx + x];
    __syncthreads();
#pragma unroll
    for (int i = 0; i < 32; i += 8) {
        float v = t[x][y + i];
        __nv_bfloat16 h = __float2bfloat16_rn(v);
        __nv_bfloat16 l = __float2bfloat16_rn(v - __bfloat162float(h));
        size_t o = (size_t)(bx + y + i) * R + by + x;
        dh[o] = h;
        dl[o] = l;
    }
}

__global__ __launch_bounds__(256)
void softmax_split(const float* __restrict__ S, __nv_bfloat16* __restrict__ Ph,
                   __nv_bfloat16* __restrict__ Pl, float* __restrict__ Rinv, int N)
{
    __shared__ float red[256];
    const int row = blockIdx.x;
    const int tid = threadIdx.x;
    const float* r = S + (size_t)row * N;

    float mx = -3.402823466e38f;
    for (int j = tid; j < N; j += 256) mx = fmaxf(mx, r[j]);
    red[tid] = mx;
    __syncthreads();
#pragma unroll
    for (int s = 128; s > 0; s >>= 1) {
        if (tid < s) red[tid] = fmaxf(red[tid], red[tid + s]);
        __syncthreads();
    }
    mx = red[0];
    __syncthreads();

    float sum = 0.f;
    for (int j = tid; j < N; j += 256) {
        float e = __expf((r[j] - mx) * SOFTMAX_SCALE);
        sum += e;
        __nv_bfloat16 h = __float2bfloat16_rn(e);
        __nv_bfloat16 l = __float2bfloat16_rn(e - __bfloat162float(h));
        Ph[(size_t)row * N + j] = h;
        Pl[(size_t)row * N + j] = l;
    }
    red[tid] = sum;
    __syncthreads();
#pragma unroll
    for (int s = 128; s > 0; s >>= 1) {
        if (tid < s) red[tid] += red[tid + s];
        __syncthreads();
    }
    if (tid == 0) Rinv[row] = 1.0f / red[0];
}

// ------------------------------- driver ------------------------------------
extern "C" void kernel_launch(void* const* d_in, const int* in_sizes, int n_in,
                              void* d_out, int out_size)
{
    const float* x  = (const float*)d_in[0];
    const float* Wq = (const float*)d_in[1];
    const float* Wk = (const float*)d_in[2];
    const float* Wv = (const float*)d_in[3];
    float* out = (float*)d_out;

    __nv_bfloat16 *xh, *xl, *Wth, *Wtl, *Qh, *Ql, *Kh, *Kl, *Vth, *Vtl, *Ph, *Pl;
    float *Vf, *S, *Rinv;
    cudaGetSymbolAddress((void**)&xh, g_xh);   cudaGetSymbolAddress((void**)&xl, g_xl);
    cudaGetSymbolAddress((void**)&Wth, g_Wth); cudaGetSymbolAddress((void**)&Wtl, g_Wtl);
    cudaGetSymbolAddress((void**)&Qh, g_Qh);   cudaGetSymbolAddress((void**)&Ql, g_Ql);
    cudaGetSymbolAddress((void**)&Kh, g_Kh);   cudaGetSymbolAddress((void**)&Kl, g_Kl);
    cudaGetSymbolAddress((void**)&Vf, g_Vf);
    cudaGetSymbolAddress((void**)&Vth, g_Vth); cudaGetSymbolAddress((void**)&Vtl, g_Vtl);
    cudaGetSymbolAddress((void**)&S, g_S);
    cudaGetSymbolAddress((void**)&Ph, g_Ph);   cudaGetSymbolAddress((void**)&Pl, g_Pl);
    cudaGetSymbolAddress((void**)&Rinv, g_Rinv);

    cudaFuncSetAttribute(gemm_hl<0>, cudaFuncAttributeMaxDynamicSharedMemorySize, SMEM_TOTAL);
    cudaFuncSetAttribute(gemm_hl<1>, cudaFuncAttributeMaxDynamicSharedMemorySize, SMEM_TOTAL);

    // 1. split x ; transpose+split weights (W[K,N] -> W^T[N,K])
    split_f32<<<(NTOK * DIM / 4 + 255) / 256, 256>>>(x, xh, xl, NTOK * DIM / 4);
    dim3 tb(32, 8);
    transpose_split<<<dim3(DIM / 32, DIM / 32), tb>>>(Wq, Wth + 0 * DIM * DIM, Wtl + 0 * DIM * DIM, DIM, DIM);
    transpose_split<<<dim3(DIM / 32, DIM / 32), tb>>>(Wk, Wth + 1 * DIM * DIM, Wtl + 1 * DIM * DIM, DIM, DIM);
    transpose_split<<<dim3(DIM / 32, DIM / 32), tb>>>(Wv, Wth + 2 * DIM * DIM, Wtl + 2 * DIM * DIM, DIM, DIM);

    // 2. projections
    dim3 blk(256);
    dim3 gProj(DIM / BN, NTOK / BM);   // (4, 32)
    gemm_hl<1><<<gProj, blk, SMEM_TOTAL>>>(xh, xl, Wth + 0 * DIM * DIM, Wtl + 0 * DIM * DIM,
                                           DIM, DIM, nullptr, Qh, Ql, nullptr);
    gemm_hl<1><<<gProj, blk, SMEM_TOTAL>>>(xh, xl, Wth + 1 * DIM * DIM, Wtl + 1 * DIM * DIM,
                                           DIM, DIM, nullptr, Kh, Kl, nullptr);
    gemm_hl<0><<<gProj, blk, SMEM_TOTAL>>>(xh, xl, Wth + 2 * DIM * DIM, Wtl + 2 * DIM * DIM,
                                           DIM, DIM, Vf, nullptr, nullptr, nullptr);

    // 3. V^T hi/lo  [DIM, NTOK]
    transpose_split<<<dim3(DIM / 32, NTOK / 32), tb>>>(Vf, Vth, Vtl, NTOK, DIM);

    // 4. S = K @ Q^T   [NTOK, NTOK]
    dim3 gS(NTOK / BN, NTOK / BM);     // (16, 32)
    gemm_hl<0><<<gS, blk, SMEM_TOTAL>>>(Kh, Kl, Qh, Ql, DIM, NTOK, S, nullptr, nullptr, nullptr);

    // 5. softmax -> P hi/lo + Rinv
    softmax_split<<<NTOK, 256>>>(S, Ph, Pl, Rinv, NTOK);

    // 6. out = (P @ V) * Rinv
    gemm_hl<0><<<gProj, blk, SMEM_TOTAL>>>(Ph, Pl, Vth, Vtl, NTOK, DIM, out,
                                           nullptr, nullptr, Rinv);
}